// round 16
// baseline (speedup 1.0000x reference)
#include <cuda_runtime.h>
#include <cuda_fp16.h>
#include <math.h>

#define VOL   128
#define VOL2  (VOL*VOL)
#define VOL3  (VOL*VOL*VOL)
#define NB    4
#define NVOX  (NB*VOL3)
#define NV4   (NVOX/4)
#define OTY   26
#define NTY   5
#define ZSEG  7
#define ZLEN  19
#define NBLK  (NTY*ZSEG*NB)   // 140 persistent blocks

#define HPINF2 0x7C007C00u
#define HNINF2 0xFC00FC00u
#define FULLM 0xffffffffu

__device__ uint2 g_yp16[NV4];
__device__ uint2 g_tru16[NV4];
__device__ uint2 g_imgA16[2*NV4];
__device__ uint2 g_imgB16[2*NV4];
__device__ uint2 g_skel16[2*NV4];
__device__ float g_yp[NVOX];
__device__ float g_acc[8];
__device__ unsigned g_bar;

__device__ __forceinline__ __half2 u2h(unsigned u) { return *reinterpret_cast<__half2*>(&u); }
__device__ __forceinline__ unsigned h2u(__half2 h) { return *reinterpret_cast<unsigned*>(&h); }

__device__ __forceinline__ uint2 hmin2u(uint2 a, uint2 b) {
    return make_uint2(h2u(__hmin2(u2h(a.x), u2h(b.x))), h2u(__hmin2(u2h(a.y), u2h(b.y))));
}
__device__ __forceinline__ uint2 hmax2u(uint2 a, uint2 b) {
    return make_uint2(h2u(__hmax2(u2h(a.x), u2h(b.x))), h2u(__hmax2(u2h(a.y), u2h(b.y))));
}
__device__ __forceinline__ uint2 hmin3u(uint2 a, uint2 b, uint2 c) { return hmin2u(hmin2u(a,b),c); }
__device__ __forceinline__ uint2 hmax3u(uint2 a, uint2 b, uint2 c) { return hmax2u(hmax2u(a,b),c); }

__device__ __forceinline__ uint2 hminS(uint2 v, int tx) {
    unsigned lb = __shfl_up_sync(FULLM, v.y, 1);
    unsigned rn = __shfl_down_sync(FULLM, v.x, 1);
    if (tx == 0)  lb = v.x << 16;
    if (tx == 31) rn = v.y >> 16;
    unsigned Lb = __byte_perm(v.x, v.y, 0x5432);
    unsigned La = __byte_perm(lb, v.x, 0x5432);
    unsigned Rb = __byte_perm(v.y, rn, 0x5432);
    uint2 L = make_uint2(La, Lb), R = make_uint2(Lb, Rb);
    return hmin3u(L, v, R);
}
__device__ __forceinline__ uint2 hmaxS(uint2 v, int tx) {
    unsigned lb = __shfl_up_sync(FULLM, v.y, 1);
    unsigned rn = __shfl_down_sync(FULLM, v.x, 1);
    if (tx == 0)  lb = v.x << 16;
    if (tx == 31) rn = v.y >> 16;
    unsigned Lb = __byte_perm(v.x, v.y, 0x5432);
    unsigned La = __byte_perm(lb, v.x, 0x5432);
    unsigned Rb = __byte_perm(v.y, rn, 0x5432);
    uint2 L = make_uint2(La, Lb), R = make_uint2(Lb, Rb);
    return hmax3u(L, v, R);
}

__device__ __forceinline__ unsigned hrelusub(unsigned a, unsigned b) {
    return h2u(__hmax2(__hsub2(u2h(a), u2h(b)), u2h(0u)));
}
__device__ __forceinline__ __half2 skupd(__half2 s, __half2 d) {
    __half2 z2 = u2h(0u);
    __half2 inc = __hmax2(__hfma2(__hneg2(s), d, d), z2);
    return __hadd2(s, inc);
}

// L2-coherent load (persistent kernel: bypass possibly-stale L1)
__device__ __forceinline__ uint2 ldcg_u2(const uint2* p) {
    uint2 r;
    asm volatile("ld.global.cg.v2.u32 {%0,%1}, [%2];" : "=r"(r.x), "=r"(r.y) : "l"(p));
    return r;
}

__global__ void zero_acc_kernel() {
    if (threadIdx.x < 8) g_acc[threadIdx.x] = 0.f;
    if (threadIdx.x == 0) g_bar = 0u;
}

// ---------------------------------------------------------------------------
// prep
// ---------------------------------------------------------------------------
__global__ __launch_bounds__(256) void prep_kernel(const float* __restrict__ pred,
                                                   const float* __restrict__ tru) {
    __shared__ float sm[3][8];
    const float4* p4 = (const float4*)pred;
    const float4* t4 = (const float4*)tru;
    float4* y4 = (float4*)g_yp;
    int base = blockIdx.x * 1024 + threadIdx.x;
    float st = 0.f, sp = 0.f, stp = 0.f;
#pragma unroll
    for (int k = 0; k < 4; k++) {
        int i = base + k * 256;
        float4 t = t4[i];
        float4 x = p4[i];
        float4 p;
        p.x = 1.f / (1.f + __expf(-x.x));
        p.y = 1.f / (1.f + __expf(-x.y));
        p.z = 1.f / (1.f + __expf(-x.z));
        p.w = 1.f / (1.f + __expf(-x.w));
        y4[i] = p;
        uint2 ph, th;
        ph.x = h2u(__halves2half2(__float2half_rn(p.x), __float2half_rn(p.y)));
        ph.y = h2u(__halves2half2(__float2half_rn(p.z), __float2half_rn(p.w)));
        th.x = h2u(__halves2half2(__float2half_rn(t.x), __float2half_rn(t.y)));
        th.y = h2u(__halves2half2(__float2half_rn(t.z), __float2half_rn(t.w)));
        g_yp16[i] = ph;
        g_tru16[i] = th;
        st  += (t.x + t.y) + (t.z + t.w);
        sp  += (p.x + p.y) + (p.z + p.w);
        stp += (t.x*p.x + t.y*p.y) + (t.z*p.z + t.w*p.w);
    }
#pragma unroll
    for (int o = 16; o > 0; o >>= 1) {
        st  += __shfl_xor_sync(FULLM, st,  o);
        sp  += __shfl_xor_sync(FULLM, sp,  o);
        stp += __shfl_xor_sync(FULLM, stp, o);
    }
    int w = threadIdx.x >> 5, lane = threadIdx.x & 31;
    if (lane == 0) { sm[0][w] = st; sm[1][w] = sp; sm[2][w] = stp; }
    __syncthreads();
    if (threadIdx.x == 0) {
        float a = 0.f, b = 0.f, c = 0.f;
#pragma unroll
        for (int i = 0; i < 8; i++) { a += sm[0][i]; b += sm[1][i]; c += sm[2][i]; }
        atomicAdd(&g_acc[0], a); atomicAdd(&g_acc[1], b); atomicAdd(&g_acc[2], c);
    }
}

// ---------------------------------------------------------------------------
// init (both chains, 280 blocks): skel = relu(x - dilate(erode(x))), imgA=erode(x)
// ---------------------------------------------------------------------------
__global__ __launch_bounds__(1024) void init_kernel() {
    __shared__ uint2 As[32][32];
    __shared__ uint2 Ms[32][32];
    const int chain = blockIdx.z >> 2;
    const int b = blockIdx.z & 3;
    const uint2* __restrict__ x = chain ? g_tru16 : g_yp16;
    const int cOff = chain * NV4;

    const int tx = threadIdx.x, ty = threadIdx.y;
    const int oz0 = blockIdx.y * ZLEN;
    const int oz1 = min(oz0 + ZLEN, VOL);
    const int gy  = blockIdx.x * OTY - 3 + ty;
    const bool vrow = (gy >= 0 && gy < VOL);
    const bool wr   = vrow && ty >= 3 && ty < 29;
    const int ym = ty > 0 ? ty - 1 : 0, yp = ty < 31 ? ty + 1 : 31;
    const int rowOff4 = b * (VOL3/4) + (vrow ? gy : 0) * (VOL/4) + tx;

    const uint2 P2 = make_uint2(HPINF2, HPINF2);
    const uint2 N2 = make_uint2(HNINF2, HNINF2);

    uint2 a_m1 = P2, a_m2 = P2, bxy_m1 = P2;
    uint2 m_m1 = N2, m_m2 = N2;
    uint2 e1_m1 = P2;

    int z0 = oz0 - 2;
    uint2 cur = P2;
    if (vrow && (unsigned)z0 < (unsigned)VOL)
        cur = x[z0 * (VOL2/4) + rowOff4];
    As[ty][tx] = cur;
    __syncthreads();

    for (int z = z0; z <= oz1 + 1; ++z) {
        uint2 nxt = P2;
        if (vrow && (unsigned)(z + 1) < (unsigned)VOL)
            nxt = x[(z + 1) * (VOL2/4) + rowOff4];

        uint2 up = As[ym][tx], dn = As[yp][tx];
        uint2 bxy = hmin3u(hminS(cur, tx), up, dn);
        uint2 e1 = hmin3u(a_m2, cur, bxy_m1);
        uint2 e1d = e1;
        if (!vrow || (unsigned)(z - 1) >= (unsigned)VOL) e1d = N2;
        uint2 hm = hmaxS(e1d, tx);
        Ms[ty][tx] = hm;
        __syncthreads();
        As[ty][tx] = nxt;
        uint2 mxy = hmax3u(hm, Ms[ym][tx], Ms[yp][tx]);
        int zo = z - 2;
        if (wr && zo >= oz0 && zo < oz1) {
            uint2 openv = hmax3u(m_m2, m_m1, mxy);
            uint2 s;
            s.x = hrelusub(a_m2.x, openv.x);
            s.y = hrelusub(a_m2.y, openv.y);
            int gi = zo * (VOL2/4) + rowOff4;
            g_skel16[cOff + gi] = s;
            g_imgA16[cOff + gi] = e1_m1;
        }
        __syncthreads();
        a_m2 = a_m1; a_m1 = cur; bxy_m1 = bxy;
        m_m2 = m_m1; m_m1 = mxy;
        e1_m1 = e1;
        cur = nxt;
    }
}

// ---------------------------------------------------------------------------
// persistent kernel: 8 phases x (chain0 sweep, chain1 sweep) + grid barrier.
// Each sweep = TWO skeleton iterations (R14 iter2 body, ldcg for imgIn).
// ---------------------------------------------------------------------------
struct RS {
    uint2 bxyA;
    uint2 m1a, m1b;
    uint2 m2a, m2b;
    uint2 d1;
    uint2 e2a, e2b;
    uint2 h1, h2;
    uint2 e1c1, e1c2, e1c3;
    uint2 a1, a2, a3;
    uint2 cur, pw;
};

__device__ __forceinline__ void sweep2(
    uint2* smemU, int tx, int tyb, int tileX, int oz0, int oz1, int b,
    const uint2* __restrict__ imgIn, uint2* __restrict__ imgOut,
    uint2* __restrict__ skel, const float* __restrict__ other,
    int doSum, float& sumS, float& sumC)
{
    const int AS0 = 0, ES0 = 2048, H10 = 4096, H20 = 6144;
    const uint2 P2 = make_uint2(HPINF2, HPINF2);
    const uint2 N2 = make_uint2(HNINF2, HNINF2);
    const uint2 Z2 = make_uint2(0u, 0u);

    bool vrow[2], wrr[2];
    int ymr[2], ypr[2], rowOff4[2], sIdx[2];
    RS st[2];
#pragma unroll
    for (int r = 0; r < 2; r++) {
        int row = tyb + r * 16;
        int gy = tileX * OTY - 3 + row;
        vrow[r] = (gy >= 0 && gy < VOL);
        wrr[r]  = vrow[r] && row >= 3 && row < 29;
        ymr[r] = row > 0 ? row - 1 : 0;
        ypr[r] = row < 31 ? row + 1 : 31;
        rowOff4[r] = b * (VOL3/4) + (vrow[r] ? gy : 0) * (VOL/4) + tx;
        sIdx[r] = row * 32 + tx;
        st[r].bxyA = P2;
        st[r].m1a = N2; st[r].m1b = N2; st[r].m2a = N2; st[r].m2b = N2;
        st[r].d1 = Z2;
        st[r].e2a = P2; st[r].e2b = P2;
        st[r].h1 = N2; st[r].h2 = N2;
        st[r].e1c1 = P2; st[r].e1c2 = P2; st[r].e1c3 = P2;
        st[r].a1 = P2; st[r].a2 = P2; st[r].a3 = P2;
    }

    const int z0 = oz0 - 3;
#pragma unroll
    for (int r = 0; r < 2; r++) {
        uint2 c = P2, p = P2;
        if (vrow[r] && (unsigned)z0 < (unsigned)VOL)
            c = ldcg_u2(imgIn + z0 * (VOL2/4) + rowOff4[r]);
        if (vrow[r] && (unsigned)(z0 + 1) < (unsigned)VOL)
            p = ldcg_u2(imgIn + (z0 + 1) * (VOL2/4) + rowOff4[r]);
        st[r].cur = c; st[r].pw = p;
        smemU[AS0 + (z0 & 1) * 1024 + sIdx[r]] = c;
        smemU[ES0 + sIdx[r]] = P2; smemU[ES0 + 1024 + sIdx[r]] = P2;
        smemU[H10 + sIdx[r]] = N2; smemU[H10 + 1024 + sIdx[r]] = N2;
        smemU[H20 + sIdx[r]] = N2; smemU[H20 + 1024 + sIdx[r]] = N2;
    }
    __syncthreads();

    for (int z = z0; z <= oz1 + 3; ++z) {
        const int sl0 = (z & 1) * 1024;
        const int sl1 = ((z + 1) & 1) * 1024;
        const int zo = z - 4;

        uint2 L[2], sPre[2];
        bool doOut[2];
        int gi[2];
#pragma unroll
        for (int r = 0; r < 2; r++) {
            L[r] = P2;
            if (vrow[r] && (unsigned)(z + 2) < (unsigned)VOL)
                L[r] = ldcg_u2(imgIn + (z + 2) * (VOL2/4) + rowOff4[r]);
            doOut[r] = wrr[r] && zo >= oz0 && zo < oz1;
            gi[r] = zo * (VOL2/4) + rowOff4[r];
            sPre[r] = Z2;
            if (doOut[r]) sPre[r] = skel[gi[r]];
        }
#pragma unroll
        for (int r = 0; r < 2; r++)
            smemU[AS0 + sl1 + sIdx[r]] = st[r].pw;

#pragma unroll
        for (int r = 0; r < 2; r++) {
            RS& s = st[r];
            uint2 upA = smemU[AS0 + sl0 + ymr[r] * 32 + tx];
            uint2 dnA = smemU[AS0 + sl0 + ypr[r] * 32 + tx];
            uint2 bxyW = hmin3u(hminS(s.cur, tx), upA, dnA);
            uint2 e1v = hmin3u(s.bxyA, s.a2, s.cur);
            bool v1 = vrow[r] && (unsigned)(z - 1) < (unsigned)VOL;
            uint2 e1p = v1 ? e1v : P2;
            uint2 e1d = v1 ? e1v : N2;
            smemU[ES0 + sl1 + sIdx[r]] = e1p;
            uint2 hm1 = hmaxS(e1d, tx);
            smemU[H10 + sl1 + sIdx[r]] = hm1;
            uint2 upE = smemU[ES0 + sl0 + ymr[r] * 32 + tx];
            uint2 dnE = smemU[ES0 + sl0 + ypr[r] * 32 + tx];
            uint2 cxy = hmin3u(hminS(s.e1c1, tx), upE, dnE);
            uint2 e2v = hmin3u(cxy, s.e1c2, e1p);
            bool v3 = vrow[r] && (unsigned)(z - 2) < (unsigned)VOL;
            uint2 e2d = v3 ? e2v : N2;
            uint2 hm2 = hmaxS(e2d, tx);
            smemU[H20 + sl0 + sIdx[r]] = hm2;
            uint2 mxy1 = hmax3u(s.h1, smemU[H10 + sl0 + ymr[r] * 32 + tx],
                                      smemU[H10 + sl0 + ypr[r] * 32 + tx]);
            uint2 open1 = hmax3u(s.m1b, s.m1a, mxy1);
            uint2 d1v;
            d1v.x = hrelusub(s.a3.x, open1.x);
            d1v.y = hrelusub(s.a3.y, open1.y);
            uint2 mxy2 = hmax3u(s.h2, smemU[H20 + sl1 + ymr[r] * 32 + tx],
                                      smemU[H20 + sl1 + ypr[r] * 32 + tx]);
            if (doOut[r]) {
                uint2 open2 = hmax3u(s.m2b, s.m2a, mxy2);
                uint2 d2;
                d2.x = hrelusub(s.e1c3.x, open2.x);
                d2.y = hrelusub(s.e1c3.y, open2.y);
                __half2 s0 = u2h(sPre[r].x), s1 = u2h(sPre[r].y);
                s0 = skupd(s0, u2h(s.d1.x));
                s1 = skupd(s1, u2h(s.d1.y));
                s0 = skupd(s0, u2h(d2.x));
                s1 = skupd(s1, u2h(d2.y));
                if (!doSum) {
                    skel[gi[r]] = make_uint2(h2u(s0), h2u(s1));
                    imgOut[gi[r]] = s.e2b;
                } else {
                    float2 f0 = __half22float2(s0), f1 = __half22float2(s1);
                    float4 o = ((const float4*)other)[gi[r]];
                    sumS += (f0.x + f0.y) + (f1.x + f1.y);
                    sumC += (f0.x*o.x + f0.y*o.y) + (f1.x*o.z + f1.y*o.w);
                }
            }
            s.bxyA = bxyW;
            s.m1b = s.m1a; s.m1a = mxy1;
            s.m2b = s.m2a; s.m2a = mxy2;
            s.d1 = d1v;
            s.e2b = s.e2a; s.e2a = e2v;
            s.h1 = hm1; s.h2 = hm2;
            s.e1c3 = s.e1c2; s.e1c2 = s.e1c1; s.e1c1 = e1p;
            s.a3 = s.a2; s.a2 = s.a1; s.a1 = s.cur;
            s.cur = s.pw; s.pw = L[r];
        }
        __syncthreads();
    }
}

__global__ __launch_bounds__(512) void persist_kernel(const float* __restrict__ tru)
{
    extern __shared__ uint2 smemU[];   // 8 * 1024 uint2 = 64 KB
    const int tx = threadIdx.x, tyb = threadIdx.y;
    const int tileX = blockIdx.x;
    const int oz0 = blockIdx.y * ZLEN;
    const int oz1 = min(oz0 + ZLEN, VOL);
    const int b = blockIdx.z;

    float sumS[2] = {0.f, 0.f}, sumC[2] = {0.f, 0.f};

    for (int phase = 0; phase < 8; ++phase) {
        int inSel = phase & 1;          // phase 0 reads A
        int doSum = (phase == 7) ? 1 : 0;
#pragma unroll 1
        for (int chain = 0; chain < 2; ++chain) {
            const int cOff = chain * NV4;
            const uint2* imgIn  = (inSel ? g_imgB16 : g_imgA16) + cOff;
            uint2* imgOut = (inSel ? g_imgA16 : g_imgB16) + cOff;
            const float* other = chain ? g_yp : tru;
            sweep2(smemU, tx, tyb, tileX, oz0, oz1, b,
                   imgIn, imgOut, g_skel16 + cOff, other,
                   doSum, sumS[chain], sumC[chain]);
        }
        if (phase < 7) {
            // grid-wide barrier (all NBLK blocks resident: 1 CTA/SM, 140 <= 148)
            if (tx == 0 && tyb == 0) {
                __threadfence();
                atomicAdd(&g_bar, 1u);
                unsigned target = (unsigned)NBLK * (unsigned)(phase + 1);
                while (*(volatile unsigned*)&g_bar < target) {}
                __threadfence();
            }
            __syncthreads();
        }
    }

    // final reductions (both chains)
#pragma unroll
    for (int c = 0; c < 2; c++) {
#pragma unroll
        for (int o = 16; o > 0; o >>= 1) {
            sumS[c] += __shfl_xor_sync(FULLM, sumS[c], o);
            sumC[c] += __shfl_xor_sync(FULLM, sumC[c], o);
        }
    }
    int tid = tyb * 32 + tx;
    int w = tid >> 5, lane = tid & 31;
    float* red = (float*)smemU;
    if (lane == 0) {
        red[w] = sumS[0]; red[16 + w] = sumC[0];
        red[32 + w] = sumS[1]; red[48 + w] = sumC[1];
    }
    __syncthreads();
    if (w == 0 && lane < 16) {
        float a = red[lane], bb = red[16 + lane];
        float c = red[32 + lane], d = red[48 + lane];
#pragma unroll
        for (int o = 8; o > 0; o >>= 1) {
            a += __shfl_xor_sync(0x0000ffffu, a, o);
            bb += __shfl_xor_sync(0x0000ffffu, bb, o);
            c += __shfl_xor_sync(0x0000ffffu, c, o);
            d += __shfl_xor_sync(0x0000ffffu, d, o);
        }
        if (lane == 0) {
            atomicAdd(&g_acc[3], a); atomicAdd(&g_acc[4], bb);
            atomicAdd(&g_acc[5], c); atomicAdd(&g_acc[6], d);
        }
    }
}

__global__ void final_kernel(float* out) {
    float st = g_acc[0], sp = g_acc[1], stp = g_acc[2];
    float skp = g_acc[3], skpt = g_acc[4], skt = g_acc[5], sktp = g_acc[6];
    float dice = 1.f - (2.f * stp + 1.f) / (st + sp + 1.f);
    float tprec = (skpt + 1.f) / (skp + 1.f);
    float tsens = (sktp + 1.f) / (skt + 1.f);
    float cl = 1.f - 2.f * (tprec * tsens) / (tprec + tsens);
    out[0] = 0.7f * dice + 0.3f * cl;
}

#define ITER_SMEM (8 * 1024 * 8)   // 64 KB

extern "C" void kernel_launch(void* const* d_in, const int* in_sizes, int n_in,
                              void* d_out, int out_size) {
    const float* pred = (const float*)d_in[0];
    const float* tru  = (const float*)d_in[1];
    float* out = (float*)d_out;

    static int smem_set = 0;
    if (!smem_set) {
        cudaFuncSetAttribute(persist_kernel, cudaFuncAttributeMaxDynamicSharedMemorySize, ITER_SMEM);
        smem_set = 1;
    }

    dim3 blkI(32, 32);
    dim3 blkP(32, 16);
    dim3 grdI(NTY, ZSEG, NB * 2);   // init: both chains, 280 blocks
    dim3 grdP(NTY, ZSEG, NB);       // persistent: 140 blocks (1/SM)

    zero_acc_kernel<<<1, 32>>>();
    prep_kernel<<<NVOX / 4096, 256>>>(pred, tru);
    init_kernel<<<grdI, blkI>>>();
    persist_kernel<<<grdP, blkP, ITER_SMEM>>>(tru);
    final_kernel<<<1, 1>>>(out);
}

// round 17
// speedup vs baseline: 1.1133x; 1.1133x over previous
#include <cuda_runtime.h>
#include <cuda_fp16.h>
#include <math.h>

#define VOL   128
#define VOL2  (VOL*VOL)
#define VOL3  (VOL*VOL*VOL)
#define NB    4
#define NVOX  (NB*VOL3)
#define NV4   (NVOX/4)
#define OTY   26
#define NTY   5
#define ZSEG  7               // 140 blocks = 1 wave
#define ZLEN  19

#define HPINF2 0x7C007C00u
#define HNINF2 0xFC00FC00u
#define FULLM 0xffffffffu

__device__ uint2 g_yp16[NV4];
__device__ uint2 g_tru16[NV4];
__device__ uint2 g_imgA16[NV4];
__device__ uint2 g_imgB16[NV4];
__device__ uint2 g_skel16[NV4];
__device__ float g_acc[8];

__device__ __forceinline__ __half2 u2h(unsigned u) { return *reinterpret_cast<__half2*>(&u); }
__device__ __forceinline__ unsigned h2u(__half2 h) { return *reinterpret_cast<unsigned*>(&h); }

__device__ __forceinline__ uint2 hmin2u(uint2 a, uint2 b) {
    return make_uint2(h2u(__hmin2(u2h(a.x), u2h(b.x))), h2u(__hmin2(u2h(a.y), u2h(b.y))));
}
__device__ __forceinline__ uint2 hmax2u(uint2 a, uint2 b) {
    return make_uint2(h2u(__hmax2(u2h(a.x), u2h(b.x))), h2u(__hmax2(u2h(a.y), u2h(b.y))));
}
__device__ __forceinline__ uint2 hmin3u(uint2 a, uint2 b, uint2 c) { return hmin2u(hmin2u(a,b),c); }
__device__ __forceinline__ uint2 hmax3u(uint2 a, uint2 b, uint2 c) { return hmax2u(hmax2u(a,b),c); }

__device__ __forceinline__ uint2 hminS(uint2 v, int tx) {
    unsigned lb = __shfl_up_sync(FULLM, v.y, 1);
    unsigned rn = __shfl_down_sync(FULLM, v.x, 1);
    if (tx == 0)  lb = v.x << 16;
    if (tx == 31) rn = v.y >> 16;
    unsigned Lb = __byte_perm(v.x, v.y, 0x5432);
    unsigned La = __byte_perm(lb, v.x, 0x5432);
    unsigned Rb = __byte_perm(v.y, rn, 0x5432);
    uint2 L = make_uint2(La, Lb), R = make_uint2(Lb, Rb);
    return hmin3u(L, v, R);
}
__device__ __forceinline__ uint2 hmaxS(uint2 v, int tx) {
    unsigned lb = __shfl_up_sync(FULLM, v.y, 1);
    unsigned rn = __shfl_down_sync(FULLM, v.x, 1);
    if (tx == 0)  lb = v.x << 16;
    if (tx == 31) rn = v.y >> 16;
    unsigned Lb = __byte_perm(v.x, v.y, 0x5432);
    unsigned La = __byte_perm(lb, v.x, 0x5432);
    unsigned Rb = __byte_perm(v.y, rn, 0x5432);
    uint2 L = make_uint2(La, Lb), R = make_uint2(Lb, Rb);
    return hmax3u(L, v, R);
}

__device__ __forceinline__ unsigned hrelusub(unsigned a, unsigned b) {
    return h2u(__hmax2(__hsub2(u2h(a), u2h(b)), u2h(0u)));
}
__device__ __forceinline__ __half2 skupd(__half2 s, __half2 d) {
    __half2 z2 = u2h(0u);
    __half2 inc = __hmax2(__hfma2(__hneg2(s), d, d), z2);
    return __hadd2(s, inc);
}

__device__ __forceinline__ const uint2* pickH(int sel) {
    if (sel == 0) return g_imgA16;
    if (sel == 1) return g_imgB16;
    if (sel == 2) return g_yp16;
    return g_tru16;
}

__global__ void zero_acc_kernel() {
    if (threadIdx.x < 8) g_acc[threadIdx.x] = 0.f;
}

// ---------------------------------------------------------------------------
// prep: yp16 = fp16(sigmoid(pred)), tru16 = fp16(tru); dice sums (fp32)
// ---------------------------------------------------------------------------
__global__ __launch_bounds__(256) void prep_kernel(const float* __restrict__ pred,
                                                   const float* __restrict__ tru) {
    __shared__ float sm[3][8];
    const float4* p4 = (const float4*)pred;
    const float4* t4 = (const float4*)tru;
    int base = blockIdx.x * 1024 + threadIdx.x;
    float st = 0.f, sp = 0.f, stp = 0.f;
#pragma unroll
    for (int k = 0; k < 4; k++) {
        int i = base + k * 256;
        float4 t = t4[i];
        float4 x = p4[i];
        float4 p;
        p.x = 1.f / (1.f + __expf(-x.x));
        p.y = 1.f / (1.f + __expf(-x.y));
        p.z = 1.f / (1.f + __expf(-x.z));
        p.w = 1.f / (1.f + __expf(-x.w));
        uint2 ph, th;
        ph.x = h2u(__halves2half2(__float2half_rn(p.x), __float2half_rn(p.y)));
        ph.y = h2u(__halves2half2(__float2half_rn(p.z), __float2half_rn(p.w)));
        th.x = h2u(__halves2half2(__float2half_rn(t.x), __float2half_rn(t.y)));
        th.y = h2u(__halves2half2(__float2half_rn(t.z), __float2half_rn(t.w)));
        g_yp16[i] = ph;
        g_tru16[i] = th;
        st  += (t.x + t.y) + (t.z + t.w);
        sp  += (p.x + p.y) + (p.z + p.w);
        stp += (t.x*p.x + t.y*p.y) + (t.z*p.z + t.w*p.w);
    }
#pragma unroll
    for (int o = 16; o > 0; o >>= 1) {
        st  += __shfl_xor_sync(FULLM, st,  o);
        sp  += __shfl_xor_sync(FULLM, sp,  o);
        stp += __shfl_xor_sync(FULLM, stp, o);
    }
    int w = threadIdx.x >> 5, lane = threadIdx.x & 31;
    if (lane == 0) { sm[0][w] = st; sm[1][w] = sp; sm[2][w] = stp; }
    __syncthreads();
    if (threadIdx.x == 0) {
        float a = 0.f, b = 0.f, c = 0.f;
#pragma unroll
        for (int i = 0; i < 8; i++) { a += sm[0][i]; b += sm[1][i]; c += sm[2][i]; }
        atomicAdd(&g_acc[0], a); atomicAdd(&g_acc[1], b); atomicAdd(&g_acc[2], c);
    }
}

// ---------------------------------------------------------------------------
// init: skel16 = relu(x - dilate(erode(x)))  AND  g_imgA16 = erode(x)
// ---------------------------------------------------------------------------
__global__ __launch_bounds__(1024) void init_kernel(int inSel) {
    __shared__ uint2 As[32][32];
    __shared__ uint2 Ms[32][32];
    const uint2* __restrict__ x = pickH(inSel);

    const int tx = threadIdx.x, ty = threadIdx.y;
    const int b   = blockIdx.z;
    const int oz0 = blockIdx.y * ZLEN;
    const int oz1 = min(oz0 + ZLEN, VOL);
    const int gy  = blockIdx.x * OTY - 3 + ty;
    const bool vrow = (gy >= 0 && gy < VOL);
    const bool wr   = vrow && ty >= 3 && ty < 29;
    const int ym = ty > 0 ? ty - 1 : 0, yp = ty < 31 ? ty + 1 : 31;
    const int rowOff4 = b * (VOL3/4) + (vrow ? gy : 0) * (VOL/4) + tx;

    const uint2 P2 = make_uint2(HPINF2, HPINF2);
    const uint2 N2 = make_uint2(HNINF2, HNINF2);

    uint2 a_m1 = P2, a_m2 = P2, bxy_m1 = P2;
    uint2 m_m1 = N2, m_m2 = N2;
    uint2 e1_m1 = P2;

    int z0 = oz0 - 2;
    uint2 cur = P2;
    if (vrow && (unsigned)z0 < (unsigned)VOL)
        cur = x[z0 * (VOL2/4) + rowOff4];
    As[ty][tx] = cur;
    __syncthreads();

    for (int z = z0; z <= oz1 + 1; ++z) {
        uint2 nxt = P2;
        if (vrow && (unsigned)(z + 1) < (unsigned)VOL)
            nxt = x[(z + 1) * (VOL2/4) + rowOff4];

        uint2 up = As[ym][tx], dn = As[yp][tx];
        uint2 bxy = hmin3u(hminS(cur, tx), up, dn);
        uint2 e1 = hmin3u(a_m2, cur, bxy_m1);
        uint2 e1d = e1;
        if (!vrow || (unsigned)(z - 1) >= (unsigned)VOL) e1d = N2;
        uint2 hm = hmaxS(e1d, tx);
        Ms[ty][tx] = hm;
        __syncthreads();
        As[ty][tx] = nxt;
        uint2 mxy = hmax3u(hm, Ms[ym][tx], Ms[yp][tx]);
        int zo = z - 2;
        if (wr && zo >= oz0 && zo < oz1) {
            uint2 openv = hmax3u(m_m2, m_m1, mxy);
            uint2 s;
            s.x = hrelusub(a_m2.x, openv.x);
            s.y = hrelusub(a_m2.y, openv.y);
            int gi = zo * (VOL2/4) + rowOff4;
            g_skel16[gi] = s;
            g_imgA16[gi] = e1_m1;
        }
        __syncthreads();
        a_m2 = a_m1; a_m1 = cur; bxy_m1 = bxy;
        m_m2 = m_m1; m_m1 = mxy;
        e1_m1 = e1;
        cur = nxt;
    }
}

// ---------------------------------------------------------------------------
// iter2: TWO skeleton iterations per launch, 512 threads, 2 rows/thread.
// Register z-history; 2-slot shared rings for y-exchange (64 KB).
// One barrier per plane. Output zo = z-4. other is fp16 (uint2).
// ---------------------------------------------------------------------------
struct RS {
    uint2 bxyA;
    uint2 m1a, m1b;
    uint2 m2a, m2b;
    uint2 d1;
    uint2 e2a, e2b;
    uint2 h1, h2;
    uint2 e1c1, e1c2, e1c3;
    uint2 a1, a2, a3;
    uint2 cur, pw;
};

__global__ __launch_bounds__(512) void iter2_kernel(
    int inSel, int outSel, int doSum, int otherSel, int accBase)
{
    extern __shared__ uint2 smemU[];   // 8 slots * 1024 uint2 = 64 KB
    const int AS0 = 0, ES0 = 2048, H10 = 4096, H20 = 6144;

    const uint2* __restrict__ imgIn = pickH(inSel);
    uint2* imgOut = (outSel == 0) ? g_imgA16 : g_imgB16;
    const uint2* __restrict__ other = pickH(otherSel);

    const int tx = threadIdx.x, tyb = threadIdx.y;
    const int b   = blockIdx.z;
    const int oz0 = blockIdx.y * ZLEN;
    const int oz1 = min(oz0 + ZLEN, VOL);

    const uint2 P2 = make_uint2(HPINF2, HPINF2);
    const uint2 N2 = make_uint2(HNINF2, HNINF2);
    const uint2 Z2 = make_uint2(0u, 0u);

    bool vrow[2], wrr[2];
    int ymr[2], ypr[2], rowOff4[2], sIdx[2];
    RS st[2];
#pragma unroll
    for (int r = 0; r < 2; r++) {
        int row = tyb + r * 16;
        int gy = blockIdx.x * OTY - 3 + row;
        vrow[r] = (gy >= 0 && gy < VOL);
        wrr[r]  = vrow[r] && row >= 3 && row < 29;
        ymr[r] = row > 0 ? row - 1 : 0;
        ypr[r] = row < 31 ? row + 1 : 31;
        rowOff4[r] = b * (VOL3/4) + (vrow[r] ? gy : 0) * (VOL/4) + tx;
        sIdx[r] = row * 32 + tx;
        st[r].bxyA = P2;
        st[r].m1a = N2; st[r].m1b = N2; st[r].m2a = N2; st[r].m2b = N2;
        st[r].d1 = Z2;
        st[r].e2a = P2; st[r].e2b = P2;
        st[r].h1 = N2; st[r].h2 = N2;
        st[r].e1c1 = P2; st[r].e1c2 = P2; st[r].e1c3 = P2;
        st[r].a1 = P2; st[r].a2 = P2; st[r].a3 = P2;
    }

    const int z0 = oz0 - 3;
#pragma unroll
    for (int r = 0; r < 2; r++) {
        uint2 c = P2, p = P2;
        if (vrow[r] && (unsigned)z0 < (unsigned)VOL)
            c = imgIn[z0 * (VOL2/4) + rowOff4[r]];
        if (vrow[r] && (unsigned)(z0 + 1) < (unsigned)VOL)
            p = imgIn[(z0 + 1) * (VOL2/4) + rowOff4[r]];
        st[r].cur = c; st[r].pw = p;
        smemU[AS0 + (z0 & 1) * 1024 + sIdx[r]] = c;
        smemU[ES0 + sIdx[r]] = P2; smemU[ES0 + 1024 + sIdx[r]] = P2;
        smemU[H10 + sIdx[r]] = N2; smemU[H10 + 1024 + sIdx[r]] = N2;
        smemU[H20 + sIdx[r]] = N2; smemU[H20 + 1024 + sIdx[r]] = N2;
    }
    float sumS = 0.f, sumC = 0.f;
    __syncthreads();

    for (int z = z0; z <= oz1 + 3; ++z) {
        const int sl0 = (z & 1) * 1024;
        const int sl1 = ((z + 1) & 1) * 1024;
        const int zo = z - 4;

        uint2 L[2], sPre[2];
        bool doOut[2];
        int gi[2];
#pragma unroll
        for (int r = 0; r < 2; r++) {
            L[r] = P2;
            if (vrow[r] && (unsigned)(z + 2) < (unsigned)VOL)
                L[r] = imgIn[(z + 2) * (VOL2/4) + rowOff4[r]];
            doOut[r] = wrr[r] && zo >= oz0 && zo < oz1;
            gi[r] = zo * (VOL2/4) + rowOff4[r];
            sPre[r] = Z2;
            if (doOut[r]) sPre[r] = g_skel16[gi[r]];
        }
#pragma unroll
        for (int r = 0; r < 2; r++)
            smemU[AS0 + sl1 + sIdx[r]] = st[r].pw;

#pragma unroll
        for (int r = 0; r < 2; r++) {
            RS& s = st[r];
            uint2 upA = smemU[AS0 + sl0 + ymr[r] * 32 + tx];
            uint2 dnA = smemU[AS0 + sl0 + ypr[r] * 32 + tx];
            uint2 bxyW = hmin3u(hminS(s.cur, tx), upA, dnA);
            uint2 e1v = hmin3u(s.bxyA, s.a2, s.cur);
            bool v1 = vrow[r] && (unsigned)(z - 1) < (unsigned)VOL;
            uint2 e1p = v1 ? e1v : P2;
            uint2 e1d = v1 ? e1v : N2;
            smemU[ES0 + sl1 + sIdx[r]] = e1p;
            uint2 hm1 = hmaxS(e1d, tx);
            smemU[H10 + sl1 + sIdx[r]] = hm1;
            uint2 upE = smemU[ES0 + sl0 + ymr[r] * 32 + tx];
            uint2 dnE = smemU[ES0 + sl0 + ypr[r] * 32 + tx];
            uint2 cxy = hmin3u(hminS(s.e1c1, tx), upE, dnE);
            uint2 e2v = hmin3u(cxy, s.e1c2, e1p);
            bool v3 = vrow[r] && (unsigned)(z - 2) < (unsigned)VOL;
            uint2 e2d = v3 ? e2v : N2;
            uint2 hm2 = hmaxS(e2d, tx);
            smemU[H20 + sl0 + sIdx[r]] = hm2;
            uint2 mxy1 = hmax3u(s.h1, smemU[H10 + sl0 + ymr[r] * 32 + tx],
                                      smemU[H10 + sl0 + ypr[r] * 32 + tx]);
            uint2 open1 = hmax3u(s.m1b, s.m1a, mxy1);
            uint2 d1v;
            d1v.x = hrelusub(s.a3.x, open1.x);
            d1v.y = hrelusub(s.a3.y, open1.y);
            uint2 mxy2 = hmax3u(s.h2, smemU[H20 + sl1 + ymr[r] * 32 + tx],
                                      smemU[H20 + sl1 + ypr[r] * 32 + tx]);
            if (doOut[r]) {
                uint2 open2 = hmax3u(s.m2b, s.m2a, mxy2);
                uint2 d2;
                d2.x = hrelusub(s.e1c3.x, open2.x);
                d2.y = hrelusub(s.e1c3.y, open2.y);
                __half2 s0 = u2h(sPre[r].x), s1 = u2h(sPre[r].y);
                s0 = skupd(s0, u2h(s.d1.x));
                s1 = skupd(s1, u2h(s.d1.y));
                s0 = skupd(s0, u2h(d2.x));
                s1 = skupd(s1, u2h(d2.y));
                if (!doSum) {
                    g_skel16[gi[r]] = make_uint2(h2u(s0), h2u(s1));
                    imgOut[gi[r]] = s.e2b;
                } else {
                    float2 f0 = __half22float2(s0), f1 = __half22float2(s1);
                    uint2 o16 = other[gi[r]];
                    float2 o0 = __half22float2(u2h(o16.x));
                    float2 o1 = __half22float2(u2h(o16.y));
                    sumS += (f0.x + f0.y) + (f1.x + f1.y);
                    sumC += (f0.x*o0.x + f0.y*o0.y) + (f1.x*o1.x + f1.y*o1.y);
                }
            }
            s.bxyA = bxyW;
            s.m1b = s.m1a; s.m1a = mxy1;
            s.m2b = s.m2a; s.m2a = mxy2;
            s.d1 = d1v;
            s.e2b = s.e2a; s.e2a = e2v;
            s.h1 = hm1; s.h2 = hm2;
            s.e1c3 = s.e1c2; s.e1c2 = s.e1c1; s.e1c1 = e1p;
            s.a3 = s.a2; s.a2 = s.a1; s.a1 = s.cur;
            s.cur = s.pw; s.pw = L[r];
        }
        __syncthreads();
    }

    if (doSum) {
#pragma unroll
        for (int o = 16; o > 0; o >>= 1) {
            sumS += __shfl_xor_sync(FULLM, sumS, o);
            sumC += __shfl_xor_sync(FULLM, sumC, o);
        }
        int tid = tyb * 32 + tx;
        int w = tid >> 5, lane = tid & 31;
        float* red = (float*)smemU;
        if (lane == 0) { red[w] = sumS; red[16 + w] = sumC; }
        __syncthreads();
        if (w == 0 && lane < 16) {
            float s = red[lane], c = red[16 + lane];
#pragma unroll
            for (int o = 8; o > 0; o >>= 1) {
                s += __shfl_xor_sync(0x0000ffffu, s, o);
                c += __shfl_xor_sync(0x0000ffffu, c, o);
            }
            if (lane == 0) {
                atomicAdd(&g_acc[accBase], s);
                atomicAdd(&g_acc[accBase + 1], c);
            }
        }
    }
}

__global__ void final_kernel(float* out) {
    float st = g_acc[0], sp = g_acc[1], stp = g_acc[2];
    float skp = g_acc[3], skpt = g_acc[4], skt = g_acc[5], sktp = g_acc[6];
    float dice = 1.f - (2.f * stp + 1.f) / (st + sp + 1.f);
    float tprec = (skpt + 1.f) / (skp + 1.f);
    float tsens = (sktp + 1.f) / (skt + 1.f);
    float cl = 1.f - 2.f * (tprec * tsens) / (tprec + tsens);
    out[0] = 0.7f * dice + 0.3f * cl;
}

#define ITER_SMEM (8 * 1024 * 8)   // 64 KB

extern "C" void kernel_launch(void* const* d_in, const int* in_sizes, int n_in,
                              void* d_out, int out_size) {
    const float* pred = (const float*)d_in[0];
    const float* tru  = (const float*)d_in[1];
    float* out = (float*)d_out;

    static int smem_set = 0;
    if (!smem_set) {
        cudaFuncSetAttribute(iter2_kernel, cudaFuncAttributeMaxDynamicSharedMemorySize, ITER_SMEM);
        smem_set = 1;
    }

    dim3 blkI(32, 32);
    dim3 blk2(32, 16);
    dim3 grd(NTY, ZSEG, NB);

    zero_acc_kernel<<<1, 32>>>();
    prep_kernel<<<NVOX / 4096, 256>>>(pred, tru);

    // ---- pred skeleton (other = tru16, accBase 3) ----
    init_kernel<<<grd, blkI>>>(2);
    for (int j = 1; j <= 8; ++j) {
        int inSel  = (j & 1) ? 0 : 1;
        int outSel = (j & 1) ? 1 : 0;
        int doSum  = (j == 8) ? 1 : 0;
        iter2_kernel<<<grd, blk2, ITER_SMEM>>>(inSel, outSel, doSum, 3, 3);
    }

    // ---- true skeleton (other = yp16, accBase 5) ----
    init_kernel<<<grd, blkI>>>(3);
    for (int j = 1; j <= 8; ++j) {
        int inSel  = (j & 1) ? 0 : 1;
        int outSel = (j & 1) ? 1 : 0;
        int doSum  = (j == 8) ? 1 : 0;
        iter2_kernel<<<grd, blk2, ITER_SMEM>>>(inSel, outSel, doSum, 2, 5);
    }

    final_kernel<<<1, 1>>>(out);
}